// round 6
// baseline (speedup 1.0000x reference)
#include <cuda_runtime.h>
#include <cuda_bf16.h>
#include <math.h>

#define MAXN 100000
#define MAXE 1600000
#define MAXET (MAXN + MAXE)

#define NEG_ATT 0.2f
#define NEG_ACT 0.01f

// ---------------- scratch ----------------
__device__ __nv_bfloat16 g_h1b[MAXN * 128];
__device__ __nv_bfloat16 g_hbb[MAXN * 128];
__device__ float g_as1[MAXN * 8];
__device__ float g_ad1[MAXN * 8];
__device__ float g_h2[MAXN * 16];
__device__ float g_as2[MAXN];
__device__ float g_ad2[MAXN];
__device__ int   g_deg[MAXN];
__device__ int   g_rs[MAXN + 1];
__device__ int   g_cur[MAXN];
__device__ int   g_esrc[MAXET];
__device__ int   g_bsum[256];

// ---------------- f32x2 helpers ----------------
__device__ __forceinline__ unsigned long long ffma2(unsigned long long a,
                                                    unsigned long long b,
                                                    unsigned long long c) {
    unsigned long long d;
    asm("fma.rn.f32x2 %0, %1, %2, %3;" : "=l"(d) : "l"(a), "l"(b), "l"(c));
    return d;
}
__device__ __forceinline__ unsigned long long pack2(float a, float b) {
    unsigned long long r;
    asm("mov.b64 %0, {%1, %2};" : "=l"(r) : "f"(a), "f"(b));
    return r;
}
__device__ __forceinline__ float2 unpack2(unsigned long long v) {
    float2 r;
    asm("mov.b64 {%0, %1}, %2;" : "=f"(r.x), "=f"(r.y) : "l"(v));
    return r;
}

__global__ void k_zero(int N) {
    int i = blockIdx.x * blockDim.x + threadIdx.x;
    if (i < N) g_deg[i] = 0;
}

// ---------------- fat kernel: GEMM1 (FFMA2) + fused alpha1  ||  hist ----------------
#define HIST_B 512
__global__ void k_fat(const float* __restrict__ x, const float* __restrict__ W,
                      const float* __restrict__ a1s, const float* __restrict__ a1d,
                      const int* __restrict__ dst, int N, int E, int GB) {
    if (blockIdx.x >= GB) {
        int b = blockIdx.x - GB;
        for (int e = b * 128 + threadIdx.x; e < E; e += 128 * HIST_B)
            atomicAdd(&g_deg[dst[e]], 1);
        return;
    }
    __shared__ float xs[32 * 128];
    int t = threadIdx.x;
    int n0 = blockIdx.x * 32;
    const float4* x4 = (const float4*)x;
    float4* xs4 = (float4*)xs;
    for (int i = t; i < 32 * 32; i += 128) {
        int row = i >> 5, c4 = i & 31;
        float4 v = make_float4(0.f, 0.f, 0.f, 0.f);
        if (n0 + row < N) v = x4[(size_t)(n0 + row) * 32 + c4];
        xs4[i] = v;
    }
    __syncthreads();

    unsigned long long acc2[32];
#pragma unroll
    for (int i = 0; i < 32; i++) acc2[i] = 0ULL;

    const ulonglong2* xsp = (const ulonglong2*)xs;
    for (int kq = 0; kq < 32; kq++) {
        int k = kq * 4;
        float w0 = __ldg(&W[(k + 0) * 128 + t]);
        float w1 = __ldg(&W[(k + 1) * 128 + t]);
        float w2 = __ldg(&W[(k + 2) * 128 + t]);
        float w3 = __ldg(&W[(k + 3) * 128 + t]);
        unsigned long long wp0 = pack2(w0, w1);
        unsigned long long wp1 = pack2(w2, w3);
#pragma unroll
        for (int nl = 0; nl < 32; nl++) {
            ulonglong2 xv = xsp[nl * 32 + kq];
            acc2[nl] = ffma2(xv.x, wp0, acc2[nl]);
            acc2[nl] = ffma2(xv.y, wp1, acc2[nl]);
        }
    }

    float asv = __ldg(&a1s[t]);
    float adv = __ldg(&a1d[t]);
    int hh = t >> 4;
    int cc = t & 15;
    int l = t & 31;
#pragma unroll
    for (int nl = 0; nl < 32; nl++) {
        float2 p = unpack2(acc2[nl]);
        float h = p.x + p.y;
        float vs = h * asv;
        float vd = h * adv;
#pragma unroll
        for (int off = 8; off; off >>= 1) {
            vs += __shfl_xor_sync(0xFFFFFFFFu, vs, off);
            vd += __shfl_xor_sync(0xFFFFFFFFu, vd, off);
        }
        float hn = __shfl_down_sync(0xFFFFFFFFu, h, 1);
        int n = n0 + nl;
        if (n < N) {
            if ((l & 1) == 0) {
                __nv_bfloat162 bv = __floats2bfloat162_rn(h, hn);
                ((__nv_bfloat162*)(g_h1b + (size_t)n * 128))[t >> 1] = bv;
            }
            if (cc == 0) {
                g_as1[n * 8 + hh] = vs;
                g_ad1[n * 8 + hh] = vd;
            }
        }
    }
}

// ---------------- scans ----------------
__global__ void k_scan1(int N) {
    __shared__ int s[512];
    int t = threadIdx.x;
    int i = blockIdx.x * 512 + t;
    s[t] = (i < N) ? g_deg[i] + 1 : 0;
    __syncthreads();
    for (int off = 256; off; off >>= 1) {
        if (t < off) s[t] += s[t + off];
        __syncthreads();
    }
    if (t == 0) g_bsum[blockIdx.x] = s[0];
}

__global__ void k_scan2(int nb, int N) {
    __shared__ int sh[8];
    int t = threadIdx.x;
    int v = (t < nb) ? g_bsum[t] : 0;
    int lane = t & 31, w = t >> 5;
    int x = v;
#pragma unroll
    for (int off = 1; off < 32; off <<= 1) {
        int y = __shfl_up_sync(0xFFFFFFFFu, x, off);
        if (lane >= off) x += y;
    }
    if (lane == 31) sh[w] = x;
    __syncthreads();
    if (w == 0) {
        int y = (lane < 8) ? sh[lane] : 0;
#pragma unroll
        for (int off = 1; off < 8; off <<= 1) {
            int z = __shfl_up_sync(0xFFFFFFFFu, y, off);
            if (lane >= off) y += z;
        }
        if (lane < 8) sh[lane] = y;
    }
    __syncthreads();
    int incl = x + (w > 0 ? sh[w - 1] : 0);
    if (t < nb) g_bsum[t] = incl - v;
    if (t == nb - 1) g_rs[N] = incl;
}

__global__ void k_scan3(int N) {
    __shared__ int s[512];
    int t = threadIdx.x;
    int i = blockIdx.x * 512 + t;
    int v = (i < N) ? g_deg[i] + 1 : 0;
    s[t] = v;
    __syncthreads();
    for (int off = 1; off < 512; off <<= 1) {
        int x = (t >= off) ? s[t - off] : 0;
        __syncthreads();
        s[t] += x;
        __syncthreads();
    }
    int excl = s[t] - v;
    if (i < N) {
        int r = g_bsum[blockIdx.x] + excl;
        g_rs[i] = r;
        g_cur[i] = r + 1;
        g_esrc[r] = i;
    }
}

__global__ void k_scatter(const int* __restrict__ src, const int* __restrict__ dst, int E) {
    int e = blockIdx.x * blockDim.x + threadIdx.x;
    if (e < E) {
        int p = atomicAdd(&g_cur[dst[e]], 1);
        g_esrc[p] = src[e];
    }
}

// ------- layer-1 gather (bf16, MLP=8): softmax + aggregate + lrelu -> hb -------
__global__ void __launch_bounds__(256) k_gather1(const float* __restrict__ b1, int N) {
    int warp = blockIdx.x * 8 + (threadIdx.x >> 5);
    if (warp >= N) return;
    int n = warp;
    int l = threadIdx.x & 31;
    int h = l >> 2;
    int beg = g_rs[n];
    int end = g_rs[n + 1];
    float adh = g_ad1[n * 8 + h];

    const uint2* h1p = (const uint2*)g_h1b;
    float4 acc = make_float4(0.f, 0.f, 0.f, 0.f);
    float ds = 0.f;

    int i = beg;
    for (; i + 8 <= end; i += 8) {
        int s[8];
#pragma unroll
        for (int j = 0; j < 8; j++) s[j] = g_esrc[i + j];
        float a[8];
        uint2 v[8];
#pragma unroll
        for (int j = 0; j < 8; j++) a[j] = g_as1[s[j] * 8 + h];
#pragma unroll
        for (int j = 0; j < 8; j++) v[j] = h1p[(size_t)s[j] * 32 + l];
#pragma unroll
        for (int j = 0; j < 8; j++) {
            float e = a[j] + adh;
            e = (e > 0.f) ? e : NEG_ATT * e;
            float ex = __expf(e);
            ds += ex;
            float2 f0 = __bfloat1622float2(*(const __nv_bfloat162*)&v[j].x);
            float2 f1 = __bfloat1622float2(*(const __nv_bfloat162*)&v[j].y);
            acc.x = fmaf(f0.x, ex, acc.x);
            acc.y = fmaf(f0.y, ex, acc.y);
            acc.z = fmaf(f1.x, ex, acc.z);
            acc.w = fmaf(f1.y, ex, acc.w);
        }
    }
    for (; i < end; i++) {
        int s = g_esrc[i];
        float a = g_as1[s * 8 + h];
        uint2 hv = h1p[(size_t)s * 32 + l];
        float e = a + adh;
        e = (e > 0.f) ? e : NEG_ATT * e;
        float ex = __expf(e);
        float2 f0 = __bfloat1622float2(*(const __nv_bfloat162*)&hv.x);
        float2 f1 = __bfloat1622float2(*(const __nv_bfloat162*)&hv.y);
        acc.x = fmaf(f0.x, ex, acc.x);
        acc.y = fmaf(f0.y, ex, acc.y);
        acc.z = fmaf(f1.x, ex, acc.z);
        acc.w = fmaf(f1.y, ex, acc.w);
        ds += ex;
    }

    float inv = 1.f / ds;
    float4 bb = ((const float4*)b1)[l];
    float4 o;
    o.x = acc.x * inv + bb.x;
    o.y = acc.y * inv + bb.y;
    o.z = acc.z * inv + bb.z;
    o.w = acc.w * inv + bb.w;
    o.x = (o.x > 0.f) ? o.x : NEG_ACT * o.x;
    o.y = (o.y > 0.f) ? o.y : NEG_ACT * o.y;
    o.z = (o.z > 0.f) ? o.z : NEG_ACT * o.z;
    o.w = (o.w > 0.f) ? o.w : NEG_ACT * o.w;

    uint2 ov;
    *(__nv_bfloat162*)&ov.x = __floats2bfloat162_rn(o.x, o.y);
    *(__nv_bfloat162*)&ov.y = __floats2bfloat162_rn(o.z, o.w);
    ((uint2*)g_hbb)[(size_t)n * 32 + l] = ov;
}

// ---------------- GEMM2 + alpha2 fused: warp per node (bf16 hb) ----------------
__global__ void k_gemm2(const float* __restrict__ W2, const float* __restrict__ a2s,
                        const float* __restrict__ a2d, int N) {
    __shared__ float W2s[128 * 16];
    int t = threadIdx.x;
    for (int i = t; i < 2048; i += 256) W2s[i] = W2[i];
    __syncthreads();

    int warp = blockIdx.x * 8 + (t >> 5);
    if (warp >= N) return;
    int n = warp;
    int l = t & 31;
    int c = l & 15;
    int half = l >> 4;

    const uint2* hb4 = (const uint2*)(g_hbb + (size_t)n * 128);
    float acc = 0.f;
#pragma unroll
    for (int k4 = 0; k4 < 16; k4++) {
        int kk = half * 16 + k4;
        uint2 hv = hb4[kk];
        float2 f0 = __bfloat1622float2(*(const __nv_bfloat162*)&hv.x);
        float2 f1 = __bfloat1622float2(*(const __nv_bfloat162*)&hv.y);
        int k = kk * 4;
        acc = fmaf(f0.x, W2s[(k + 0) * 16 + c], acc);
        acc = fmaf(f0.y, W2s[(k + 1) * 16 + c], acc);
        acc = fmaf(f1.x, W2s[(k + 2) * 16 + c], acc);
        acc = fmaf(f1.y, W2s[(k + 3) * 16 + c], acc);
    }
    acc += __shfl_xor_sync(0xFFFFFFFFu, acc, 16);
    if (half == 0) g_h2[n * 16 + c] = acc;

    float vs = acc * __ldg(&a2s[c]);
    float vd = acc * __ldg(&a2d[c]);
#pragma unroll
    for (int off = 8; off; off >>= 1) {
        vs += __shfl_xor_sync(0xFFFFFFFFu, vs, off);
        vd += __shfl_xor_sync(0xFFFFFFFFu, vd, off);
    }
    if (l == 0) { g_as2[n] = vs; g_ad2[n] = vd; }
}

// ---------------- layer-2 gather + final softmax (MLP=8 per half-warp) ----------------
__global__ void __launch_bounds__(256) k_gather2(const float* __restrict__ b2,
                                                 float* __restrict__ out, int N) {
    int warp = blockIdx.x * 8 + (threadIdx.x >> 5);
    if (warp >= N) return;
    int n = warp;
    int l = threadIdx.x & 31;
    int c = l & 15;
    int half = l >> 4;
    int beg = g_rs[n];
    int cnt = g_rs[n + 1] - beg;
    float ad = g_ad2[n];

    float acc = 0.f, ds = 0.f;
    int j = half;
    for (; j + 14 < cnt; j += 16) {
        int s[8];
#pragma unroll
        for (int q = 0; q < 8; q++) s[q] = g_esrc[beg + j + 2 * q];
        float a[8], hv[8];
#pragma unroll
        for (int q = 0; q < 8; q++) a[q] = g_as2[s[q]];
#pragma unroll
        for (int q = 0; q < 8; q++) hv[q] = g_h2[s[q] * 16 + c];
#pragma unroll
        for (int q = 0; q < 8; q++) {
            float e = a[q] + ad;
            e = (e > 0.f) ? e : NEG_ATT * e;
            float ex = __expf(e);
            ds += ex;
            acc = fmaf(hv[q], ex, acc);
        }
    }
    for (; j < cnt; j += 2) {
        int s = g_esrc[beg + j];
        float e = g_as2[s] + ad;
        e = (e > 0.f) ? e : NEG_ATT * e;
        float ex = __expf(e);
        float hv = g_h2[s * 16 + c];
        acc = fmaf(hv, ex, acc);
        ds += ex;
    }
    acc += __shfl_xor_sync(0xFFFFFFFFu, acc, 16);
    ds += __shfl_xor_sync(0xFFFFFFFFu, ds, 16);

    float o = acc / ds + __ldg(&b2[c]);
    float m = o;
#pragma unroll
    for (int off = 8; off; off >>= 1) m = fmaxf(m, __shfl_xor_sync(0xFFFFFFFFu, m, off));
    float ex = __expf(o - m);
    float sm = ex;
#pragma unroll
    for (int off = 8; off; off >>= 1) sm += __shfl_xor_sync(0xFFFFFFFFu, sm, off);
    if (l < 16) out[(size_t)n * 16 + c] = ex / sm;
}

// ---------------- launch ----------------
extern "C" void kernel_launch(void* const* d_in, const int* in_sizes, int n_in,
                              void* d_out, int out_size) {
    const float* x   = (const float*)d_in[0];
    const int*   ei  = (const int*)d_in[1];
    const float* W1  = (const float*)d_in[2];
    const float* a1s = (const float*)d_in[3];
    const float* a1d = (const float*)d_in[4];
    const float* b1  = (const float*)d_in[5];
    const float* W2  = (const float*)d_in[6];
    const float* a2s = (const float*)d_in[7];
    const float* a2d = (const float*)d_in[8];
    const float* b2  = (const float*)d_in[9];
    float* out = (float*)d_out;

    int N = in_sizes[0] / 128;
    int E = in_sizes[1] / 2;
    const int* src = ei;
    const int* dst = ei + E;

    int nbScan = (N + 511) / 512;
    int GB = (N + 31) / 32;

    k_zero<<<(N + 511) / 512, 512>>>(N);
    k_fat<<<GB + HIST_B, 128>>>(x, W1, a1s, a1d, dst, N, E, GB);
    k_scan1<<<nbScan, 512>>>(N);
    k_scan2<<<1, 256>>>(nbScan, N);
    k_scan3<<<nbScan, 512>>>(N);
    k_scatter<<<(E + 255) / 256, 256>>>(src, dst, E);

    k_gather1<<<(N + 7) / 8, 256>>>(b1, N);
    k_gemm2<<<(N + 7) / 8, 256>>>(W2, a2s, a2d, N);
    k_gather2<<<(N + 7) / 8, 256>>>(b2, out, N);
}

// round 7
// speedup vs baseline: 1.0932x; 1.0932x over previous
#include <cuda_runtime.h>
#include <cuda_bf16.h>
#include <math.h>

#define MAXN 100000
#define MAXE 1600000
#define MAXET (MAXN + MAXE)

#define NEG_ATT 0.2f
#define NEG_ACT 0.01f

// ---------------- scratch ----------------
__device__ __nv_bfloat16 g_h1b[MAXN * 128];
__device__ float g_as1[MAXN * 8];
__device__ float g_ad1[MAXN * 8];
__device__ float g_h2[MAXN * 16];
__device__ float g_as2[MAXN];
__device__ float g_ad2[MAXN];
__device__ int   g_deg[MAXN];      // zero at load; re-zeroed by k_scan3 each call
__device__ int   g_rs[MAXN + 1];
__device__ int   g_cur[MAXN];
__device__ int   g_esrc[MAXET];
__device__ int   g_bsum[256];

// ---------------- f32x2 helpers ----------------
__device__ __forceinline__ unsigned long long ffma2(unsigned long long a,
                                                    unsigned long long b,
                                                    unsigned long long c) {
    unsigned long long d;
    asm("fma.rn.f32x2 %0, %1, %2, %3;" : "=l"(d) : "l"(a), "l"(b), "l"(c));
    return d;
}
__device__ __forceinline__ unsigned long long pack2(float a, float b) {
    unsigned long long r;
    asm("mov.b64 %0, {%1, %2};" : "=l"(r) : "f"(a), "f"(b));
    return r;
}
__device__ __forceinline__ float2 unpack2(unsigned long long v) {
    float2 r;
    asm("mov.b64 {%0, %1}, %2;" : "=f"(r.x), "=f"(r.y) : "l"(v));
    return r;
}

// ---------------- fat kernel: GEMM1 (FFMA2) + fused alpha1  ||  hist ----------------
#define HIST_B 512
__global__ void k_fat(const float* __restrict__ x, const float* __restrict__ W,
                      const float* __restrict__ a1s, const float* __restrict__ a1d,
                      const int* __restrict__ dst, int N, int E, int GB) {
    if (blockIdx.x >= GB) {
        int b = blockIdx.x - GB;
        for (int e = b * 128 + threadIdx.x; e < E; e += 128 * HIST_B)
            atomicAdd(&g_deg[dst[e]], 1);
        return;
    }
    __shared__ float xs[32 * 128];
    int t = threadIdx.x;
    int n0 = blockIdx.x * 32;
    const float4* x4 = (const float4*)x;
    float4* xs4 = (float4*)xs;
    for (int i = t; i < 32 * 32; i += 128) {
        int row = i >> 5, c4 = i & 31;
        float4 v = make_float4(0.f, 0.f, 0.f, 0.f);
        if (n0 + row < N) v = x4[(size_t)(n0 + row) * 32 + c4];
        xs4[i] = v;
    }
    __syncthreads();

    unsigned long long acc2[32];
#pragma unroll
    for (int i = 0; i < 32; i++) acc2[i] = 0ULL;

    const ulonglong2* xsp = (const ulonglong2*)xs;
    for (int kq = 0; kq < 32; kq++) {
        int k = kq * 4;
        float w0 = __ldg(&W[(k + 0) * 128 + t]);
        float w1 = __ldg(&W[(k + 1) * 128 + t]);
        float w2 = __ldg(&W[(k + 2) * 128 + t]);
        float w3 = __ldg(&W[(k + 3) * 128 + t]);
        unsigned long long wp0 = pack2(w0, w1);
        unsigned long long wp1 = pack2(w2, w3);
#pragma unroll
        for (int nl = 0; nl < 32; nl++) {
            ulonglong2 xv = xsp[nl * 32 + kq];
            acc2[nl] = ffma2(xv.x, wp0, acc2[nl]);
            acc2[nl] = ffma2(xv.y, wp1, acc2[nl]);
        }
    }

    float asv = __ldg(&a1s[t]);
    float adv = __ldg(&a1d[t]);
    int hh = t >> 4;
    int cc = t & 15;
    int l = t & 31;
#pragma unroll
    for (int nl = 0; nl < 32; nl++) {
        float2 p = unpack2(acc2[nl]);
        float h = p.x + p.y;
        float vs = h * asv;
        float vd = h * adv;
#pragma unroll
        for (int off = 8; off; off >>= 1) {
            vs += __shfl_xor_sync(0xFFFFFFFFu, vs, off);
            vd += __shfl_xor_sync(0xFFFFFFFFu, vd, off);
        }
        float hn = __shfl_down_sync(0xFFFFFFFFu, h, 1);
        int n = n0 + nl;
        if (n < N) {
            if ((l & 1) == 0) {
                __nv_bfloat162 bv = __floats2bfloat162_rn(h, hn);
                ((__nv_bfloat162*)(g_h1b + (size_t)n * 128))[t >> 1] = bv;
            }
            if (cc == 0) {
                g_as1[n * 8 + hh] = vs;
                g_ad1[n * 8 + hh] = vd;
            }
        }
    }
}

// ---------------- scans ----------------
__global__ void k_scan1(int N) {
    __shared__ int s[512];
    int t = threadIdx.x;
    int i = blockIdx.x * 512 + t;
    s[t] = (i < N) ? g_deg[i] + 1 : 0;
    __syncthreads();
    for (int off = 256; off; off >>= 1) {
        if (t < off) s[t] += s[t + off];
        __syncthreads();
    }
    if (t == 0) g_bsum[blockIdx.x] = s[0];
}

__global__ void k_scan2(int nb, int N) {
    __shared__ int sh[8];
    int t = threadIdx.x;
    int v = (t < nb) ? g_bsum[t] : 0;
    int lane = t & 31, w = t >> 5;
    int x = v;
#pragma unroll
    for (int off = 1; off < 32; off <<= 1) {
        int y = __shfl_up_sync(0xFFFFFFFFu, x, off);
        if (lane >= off) x += y;
    }
    if (lane == 31) sh[w] = x;
    __syncthreads();
    if (w == 0) {
        int y = (lane < 8) ? sh[lane] : 0;
#pragma unroll
        for (int off = 1; off < 8; off <<= 1) {
            int z = __shfl_up_sync(0xFFFFFFFFu, y, off);
            if (lane >= off) y += z;
        }
        if (lane < 8) sh[lane] = y;
    }
    __syncthreads();
    int incl = x + (w > 0 ? sh[w - 1] : 0);
    if (t < nb) g_bsum[t] = incl - v;
    if (t == nb - 1) g_rs[N] = incl;
}

__global__ void k_scan3(int N) {
    __shared__ int s[512];
    int t = threadIdx.x;
    int i = blockIdx.x * 512 + t;
    int v = (i < N) ? g_deg[i] + 1 : 0;
    s[t] = v;
    __syncthreads();
    for (int off = 1; off < 512; off <<= 1) {
        int x = (t >= off) ? s[t - off] : 0;
        __syncthreads();
        s[t] += x;
        __syncthreads();
    }
    int excl = s[t] - v;
    if (i < N) {
        int r = g_bsum[blockIdx.x] + excl;
        g_rs[i] = r;
        g_cur[i] = r + 1;
        g_esrc[r] = i;
        g_deg[i] = 0;          // reset for next call (graph replay invariant)
    }
}

__global__ void k_scatter(const int* __restrict__ src, const int* __restrict__ dst, int E) {
    int e = blockIdx.x * blockDim.x + threadIdx.x;
    if (e < E) {
        int p = atomicAdd(&g_cur[dst[e]], 1);
        g_esrc[p] = src[e];
    }
}

// ------- layer-1 gather (bf16, MLP=4) + softmax + lrelu + fused GEMM2 (smem) -------
__global__ void __launch_bounds__(256) k_gather1(const float* __restrict__ b1,
                                                 const float* __restrict__ W2,
                                                 const float* __restrict__ a2s,
                                                 const float* __restrict__ a2d,
                                                 int N) {
    __shared__ float W2s[128 * 16];
    __shared__ float hbs[8][132];     // per-warp hb row (pad to dodge bank aliasing)
    int t = threadIdx.x;
    for (int i = t; i < 2048; i += 256) W2s[i] = W2[i];
    __syncthreads();

    int wib = t >> 5;
    int warp = blockIdx.x * 8 + wib;
    if (warp >= N) return;
    int n = warp;
    int l = t & 31;
    int h = l >> 2;
    int beg = g_rs[n];
    int end = g_rs[n + 1];
    float adh = g_ad1[n * 8 + h];

    const uint2* h1p = (const uint2*)g_h1b;
    float4 acc = make_float4(0.f, 0.f, 0.f, 0.f);
    float ds = 0.f;

    int i = beg;
    for (; i + 4 <= end; i += 4) {
        int s0 = g_esrc[i + 0];
        int s1 = g_esrc[i + 1];
        int s2 = g_esrc[i + 2];
        int s3 = g_esrc[i + 3];
        float a0 = g_as1[s0 * 8 + h];
        float a1 = g_as1[s1 * 8 + h];
        float a2 = g_as1[s2 * 8 + h];
        float a3 = g_as1[s3 * 8 + h];
        uint2 v0 = h1p[(size_t)s0 * 32 + l];
        uint2 v1 = h1p[(size_t)s1 * 32 + l];
        uint2 v2 = h1p[(size_t)s2 * 32 + l];
        uint2 v3 = h1p[(size_t)s3 * 32 + l];
        float e0 = a0 + adh; e0 = (e0 > 0.f) ? e0 : NEG_ATT * e0;
        float e1 = a1 + adh; e1 = (e1 > 0.f) ? e1 : NEG_ATT * e1;
        float e2 = a2 + adh; e2 = (e2 > 0.f) ? e2 : NEG_ATT * e2;
        float e3 = a3 + adh; e3 = (e3 > 0.f) ? e3 : NEG_ATT * e3;
        float x0 = __expf(e0), x1 = __expf(e1), x2 = __expf(e2), x3 = __expf(e3);
        ds += (x0 + x1) + (x2 + x3);
        {
            float2 f0 = __bfloat1622float2(*(const __nv_bfloat162*)&v0.x);
            float2 f1 = __bfloat1622float2(*(const __nv_bfloat162*)&v0.y);
            acc.x = fmaf(f0.x, x0, acc.x); acc.y = fmaf(f0.y, x0, acc.y);
            acc.z = fmaf(f1.x, x0, acc.z); acc.w = fmaf(f1.y, x0, acc.w);
        }
        {
            float2 f0 = __bfloat1622float2(*(const __nv_bfloat162*)&v1.x);
            float2 f1 = __bfloat1622float2(*(const __nv_bfloat162*)&v1.y);
            acc.x = fmaf(f0.x, x1, acc.x); acc.y = fmaf(f0.y, x1, acc.y);
            acc.z = fmaf(f1.x, x1, acc.z); acc.w = fmaf(f1.y, x1, acc.w);
        }
        {
            float2 f0 = __bfloat1622float2(*(const __nv_bfloat162*)&v2.x);
            float2 f1 = __bfloat1622float2(*(const __nv_bfloat162*)&v2.y);
            acc.x = fmaf(f0.x, x2, acc.x); acc.y = fmaf(f0.y, x2, acc.y);
            acc.z = fmaf(f1.x, x2, acc.z); acc.w = fmaf(f1.y, x2, acc.w);
        }
        {
            float2 f0 = __bfloat1622float2(*(const __nv_bfloat162*)&v3.x);
            float2 f1 = __bfloat1622float2(*(const __nv_bfloat162*)&v3.y);
            acc.x = fmaf(f0.x, x3, acc.x); acc.y = fmaf(f0.y, x3, acc.y);
            acc.z = fmaf(f1.x, x3, acc.z); acc.w = fmaf(f1.y, x3, acc.w);
        }
    }
    for (; i < end; i++) {
        int s = g_esrc[i];
        float a = g_as1[s * 8 + h];
        uint2 hv = h1p[(size_t)s * 32 + l];
        float e = a + adh;
        e = (e > 0.f) ? e : NEG_ATT * e;
        float ex = __expf(e);
        float2 f0 = __bfloat1622float2(*(const __nv_bfloat162*)&hv.x);
        float2 f1 = __bfloat1622float2(*(const __nv_bfloat162*)&hv.y);
        acc.x = fmaf(f0.x, ex, acc.x);
        acc.y = fmaf(f0.y, ex, acc.y);
        acc.z = fmaf(f1.x, ex, acc.z);
        acc.w = fmaf(f1.y, ex, acc.w);
        ds += ex;
    }

    float inv = 1.f / ds;
    float4 bb = ((const float4*)b1)[l];
    float4 o;
    o.x = acc.x * inv + bb.x;
    o.y = acc.y * inv + bb.y;
    o.z = acc.z * inv + bb.z;
    o.w = acc.w * inv + bb.w;
    o.x = (o.x > 0.f) ? o.x : NEG_ACT * o.x;
    o.y = (o.y > 0.f) ? o.y : NEG_ACT * o.y;
    o.z = (o.z > 0.f) ? o.z : NEG_ACT * o.z;
    o.w = (o.w > 0.f) ? o.w : NEG_ACT * o.w;

    // stage hb row in this warp's smem row (no cross-warp sharing)
    hbs[wib][4 * l + 0] = o.x;
    hbs[wib][4 * l + 1] = o.y;
    hbs[wib][4 * l + 2] = o.z;
    hbs[wib][4 * l + 3] = o.w;
    __syncwarp();

    // fused GEMM2: lane (c = l&15, half = l>>4) accumulates over its 64 k values
    int c = l & 15;
    int half = l >> 4;
    const float* hrow = hbs[wib] + half * 64;
    float g2 = 0.f;
#pragma unroll
    for (int k4 = 0; k4 < 16; k4++) {
        int k = half * 64 + k4 * 4;
        float h0 = hrow[k4 * 4 + 0];
        float h1 = hrow[k4 * 4 + 1];
        float h2 = hrow[k4 * 4 + 2];
        float h3 = hrow[k4 * 4 + 3];
        g2 = fmaf(h0, W2s[(k + 0) * 16 + c], g2);
        g2 = fmaf(h1, W2s[(k + 1) * 16 + c], g2);
        g2 = fmaf(h2, W2s[(k + 2) * 16 + c], g2);
        g2 = fmaf(h3, W2s[(k + 3) * 16 + c], g2);
    }
    g2 += __shfl_xor_sync(0xFFFFFFFFu, g2, 16);
    if (half == 0) g_h2[n * 16 + c] = g2;

    float vs = g2 * __ldg(&a2s[c]);
    float vd = g2 * __ldg(&a2d[c]);
#pragma unroll
    for (int off = 8; off; off >>= 1) {
        vs += __shfl_xor_sync(0xFFFFFFFFu, vs, off);
        vd += __shfl_xor_sync(0xFFFFFFFFu, vd, off);
    }
    if (l == 0) { g_as2[n] = vs; g_ad2[n] = vd; }
}

// ---------------- layer-2 gather + final softmax (MLP=4 per half-warp) ----------------
__global__ void __launch_bounds__(256) k_gather2(const float* __restrict__ b2,
                                                 float* __restrict__ out, int N) {
    int warp = blockIdx.x * 8 + (threadIdx.x >> 5);
    if (warp >= N) return;
    int n = warp;
    int l = threadIdx.x & 31;
    int c = l & 15;
    int half = l >> 4;
    int beg = g_rs[n];
    int cnt = g_rs[n + 1] - beg;
    float ad = g_ad2[n];

    float acc = 0.f, ds = 0.f;
    int j = half;
    for (; j + 6 < cnt; j += 8) {
        int s0 = g_esrc[beg + j + 0];
        int s1 = g_esrc[beg + j + 2];
        int s2 = g_esrc[beg + j + 4];
        int s3 = g_esrc[beg + j + 6];
        float e0 = g_as2[s0] + ad; e0 = (e0 > 0.f) ? e0 : NEG_ATT * e0;
        float e1 = g_as2[s1] + ad; e1 = (e1 > 0.f) ? e1 : NEG_ATT * e1;
        float e2 = g_as2[s2] + ad; e2 = (e2 > 0.f) ? e2 : NEG_ATT * e2;
        float e3 = g_as2[s3] + ad; e3 = (e3 > 0.f) ? e3 : NEG_ATT * e3;
        float h0 = g_h2[s0 * 16 + c];
        float h1 = g_h2[s1 * 16 + c];
        float h2 = g_h2[s2 * 16 + c];
        float h3 = g_h2[s3 * 16 + c];
        float x0 = __expf(e0), x1 = __expf(e1), x2 = __expf(e2), x3 = __expf(e3);
        ds += (x0 + x1) + (x2 + x3);
        acc = fmaf(h0, x0, acc);
        acc = fmaf(h1, x1, acc);
        acc = fmaf(h2, x2, acc);
        acc = fmaf(h3, x3, acc);
    }
    for (; j < cnt; j += 2) {
        int s = g_esrc[beg + j];
        float e = g_as2[s] + ad;
        e = (e > 0.f) ? e : NEG_ATT * e;
        float ex = __expf(e);
        float hv = g_h2[s * 16 + c];
        acc = fmaf(hv, ex, acc);
        ds += ex;
    }
    acc += __shfl_xor_sync(0xFFFFFFFFu, acc, 16);
    ds += __shfl_xor_sync(0xFFFFFFFFu, ds, 16);

    float o = acc / ds + __ldg(&b2[c]);
    float m = o;
#pragma unroll
    for (int off = 8; off; off >>= 1) m = fmaxf(m, __shfl_xor_sync(0xFFFFFFFFu, m, off));
    float ex = __expf(o - m);
    float sm = ex;
#pragma unroll
    for (int off = 8; off; off >>= 1) sm += __shfl_xor_sync(0xFFFFFFFFu, sm, off);
    if (l < 16) out[(size_t)n * 16 + c] = ex / sm;
}

// ---------------- launch ----------------
extern "C" void kernel_launch(void* const* d_in, const int* in_sizes, int n_in,
                              void* d_out, int out_size) {
    const float* x   = (const float*)d_in[0];
    const int*   ei  = (const int*)d_in[1];
    const float* W1  = (const float*)d_in[2];
    const float* a1s = (const float*)d_in[3];
    const float* a1d = (const float*)d_in[4];
    const float* b1  = (const float*)d_in[5];
    const float* W2  = (const float*)d_in[6];
    const float* a2s = (const float*)d_in[7];
    const float* a2d = (const float*)d_in[8];
    const float* b2  = (const float*)d_in[9];
    float* out = (float*)d_out;

    int N = in_sizes[0] / 128;
    int E = in_sizes[1] / 2;
    const int* src = ei;
    const int* dst = ei + E;

    int nbScan = (N + 511) / 512;
    int GB = (N + 31) / 32;

    k_fat<<<GB + HIST_B, 128>>>(x, W1, a1s, a1d, dst, N, E, GB);
    k_scan1<<<nbScan, 512>>>(N);
    k_scan2<<<1, 256>>>(nbScan, N);
    k_scan3<<<nbScan, 512>>>(N);
    k_scatter<<<(E + 255) / 256, 256>>>(src, dst, E);

    k_gather1<<<(N + 7) / 8, 256>>>(b1, W2, a2s, a2d, N);
    k_gather2<<<(N + 7) / 8, 256>>>(b2, out, N);
}